// round 12
// baseline (speedup 1.0000x reference)
#include <cuda_runtime.h>

#define NCAM 6
#define CCH  128
#define H0   32
#define W0   88
#define H1   16
#define W1   44
#define H0P  (H0+2)       // 34
#define W0P  (W0+2)       // 90
#define H1P  (H1+2)       // 18
#define W1P  (W1+2)       // 46
#define HW0  (H0*W0)      // 2816
#define HW1  (H1*W1)      // 704
#define QDIM 16384
#define PPTS 4
#define NTASK (QDIM * PPTS)
#define NPAIR (NTASK / 2)         // 32768 task pairs
#define EPSF 1e-5f
#define FULLMASK 0xffffffffu

#define NSM       152
#define BLKPER_SM 8
#define NBLKMAIN  (NSM * BLKPER_SM)          // 1216 blocks = one full wave
#define NWARPS    (NBLKMAIN * 8)             // 9728 persistent warps

// Transposed + zero-padded feature scratch: [N, H+2, W+2, C].
// Borders never written; __device__ globals are zero-initialized, so
// out-of-range bilinear corners read exact zeros (padding_mode='zeros').
__device__ float g_f0t[NCAM * H0P * W0P * CCH];   // ~9.4 MB
__device__ float g_f1t[NCAM * H1P * W1P * CCH];   // ~2.5 MB

// -------------------------------------------------------------------------
// SMEM-tiled transpose with float4 I/O: [C=128, HW] -> padded [H+2, W+2, C].
// -------------------------------------------------------------------------
#define NBLK0 (NCAM * 4 * (HW0/32))   // 2112
#define NBLK1 (NCAM * 4 * (HW1/32))   // 528

__global__ void __launch_bounds__(256)
transpose_feats_kernel(const float* __restrict__ f0,
                       const float* __restrict__ f1) {
    __shared__ float tile[32][33];

    int b = blockIdx.x;
    const float* __restrict__ src;
    float* __restrict__ dst;
    int n, ct, hwt, HW, W, WP;
    if (b < NBLK0) {
        n = b / (4 * (HW0/32));
        int r = b % (4 * (HW0/32));
        ct = r & 3; hwt = r >> 2;
        src = f0; dst = g_f0t; HW = HW0; W = W0; WP = W0P;
    } else {
        b -= NBLK0;
        n = b / (4 * (HW1/32));
        int r = b % (4 * (HW1/32));
        ct = r & 3; hwt = r >> 2;
        src = f1; dst = g_f1t; HW = HW1; W = W1; WP = W1P;
    }

    {
        int c   = threadIdx.x >> 3;
        int hw4 = (threadIdx.x & 7) * 4;
        const float4 v = *reinterpret_cast<const float4*>(
            src + (size_t)n * CCH * HW + (size_t)(ct*32 + c) * HW + hwt*32 + hw4);
        tile[hw4 + 0][c] = v.x;
        tile[hw4 + 1][c] = v.y;
        tile[hw4 + 2][c] = v.z;
        tile[hw4 + 3][c] = v.w;
    }
    __syncthreads();

    {
        int hw = threadIdx.x >> 3;
        int c4 = (threadIdx.x & 7) * 4;
        float4 v;
        v.x = tile[hw][c4 + 0];
        v.y = tile[hw][c4 + 1];
        v.z = tile[hw][c4 + 2];
        v.w = tile[hw][c4 + 3];
        int hwglob = hwt * 32 + hw;
        int h = hwglob / W;
        int w = hwglob - h * W;
        size_t HPWP = (size_t)(W == W0 ? H0P * W0P : H1P * W1P);
        size_t off = ((size_t)n * HPWP + (size_t)(h + 1) * WP + (w + 1)) * CCH
                   + ct * 32 + c4;
        *reinterpret_cast<float4*>(dst + off) = v;
    }
}

// -------------------------------------------------------------------------
// Main sampling kernel: persistent single-wave grid; each warp grid-strides
// over task pairs (2 tasks per iteration; lanes 0-5 / 8-13 project).
// -------------------------------------------------------------------------

__device__ __forceinline__ void gacc(const char* __restrict__ base, int byteoff,
                                     float w,
                                     unsigned long long& aA, unsigned long long& aB) {
    ulonglong2 v = *reinterpret_cast<const ulonglong2*>(base + byteoff);
    unsigned long long wp;
    asm("mov.b64 %0, {%1, %1};" : "=l"(wp) : "f"(w));
    asm("fma.rn.f32x2 %0, %1, %2, %0;" : "+l"(aA) : "l"(v.x), "l"(wp));
    asm("fma.rn.f32x2 %0, %1, %2, %0;" : "+l"(aB) : "l"(v.y), "l"(wp));
}

// Clamp-free bilinear sample of one padded level; u,v warp-uniform.
__device__ __forceinline__ void sample_level(const char* __restrict__ base,
                                             float u, float v, int cambase,
                                             int Wl, int Hl, int WP,
                                             unsigned long long& aA,
                                             unsigned long long& aB) {
    float px = fmaf(u, (float)Wl, 0.5f);
    float py = fmaf(v, (float)Hl, 0.5f);
    int x0 = __float2int_rd(px);
    int y0 = __float2int_rd(py);
    float wx1 = px - __int2float_rn(x0);
    float wy1 = py - __int2float_rn(y0);
    float wx0 = 1.0f - wx1;
    float wy0 = 1.0f - wy1;

    int o00 = (cambase + y0 * WP + x0) << 9;   // *CCH*4 bytes
    int rowB = WP << 9;
    gacc(base, o00,              wx0 * wy0, aA, aB);
    gacc(base, o00 + 512,        wx1 * wy0, aA, aB);
    gacc(base, o00 + rowB,       wx0 * wy1, aA, aB);
    gacc(base, o00 + rowB + 512, wx1 * wy1, aA, aB);
}

__device__ __forceinline__ void task_gather(unsigned vmk, int shbase,
                                            float u, float v,
                                            const char* __restrict__ b0,
                                            const char* __restrict__ b1,
                                            float* __restrict__ dst) {
    if (vmk == 0u) {
        *reinterpret_cast<float4*>(dst) = make_float4(0.f, 0.f, 0.f, 0.f);
        return;
    }
    unsigned long long aA = 0ull, aB = 0ull;
#pragma unroll
    for (int c = 0; c < NCAM; c++) {
        if (vmk & (1u << c)) {
            float uu = __shfl_sync(FULLMASK, u, shbase + c);
            float vv = __shfl_sync(FULLMASK, v, shbase + c);
            sample_level(b0, uu, vv, c * (H0P * W0P), W0, H0, W0P, aA, aB);
            sample_level(b1, uu, vv, c * (H1P * W1P), W1, H1, W1P, aA, aB);
        }
    }
    float scale = 0.5f / (float)__popc(vmk);
    float ax, ay, az, aw;
    asm("mov.b64 {%0, %1}, %2;" : "=f"(ax), "=f"(ay) : "l"(aA));
    asm("mov.b64 {%0, %1}, %2;" : "=f"(az), "=f"(aw) : "l"(aB));
    float4 o;
    o.x = ax * scale; o.y = ay * scale;
    o.z = az * scale; o.w = aw * scale;
    *reinterpret_cast<float4*>(dst) = o;
}

__global__ void __launch_bounds__(256, 8)
bev_sample_kernel(const float* __restrict__ refpts,
                  const float* __restrict__ lidar2img,
                  float* __restrict__ out) {
    __shared__ float sM[NCAM * 16];
    int tid = threadIdx.x;

    // Pre-multiply: M' = diag(1/704, 1/256, 1, 1) * M * Affine(pc_range).
    if (tid < NCAM * 4) {
        int n = tid >> 2, r = tid & 3;
        const float* Mr = lidar2img + n * 16 + r * 4;
        float m0 = Mr[0], m1 = Mr[1], m2 = Mr[2], m3 = Mr[3];
        float p0 = m0 * 102.4f;
        float p1 = m1 * 102.4f;
        float p2 = m2 * 8.0f;
        float p3 = fmaf(m0, -51.2f, fmaf(m1, -51.2f, fmaf(m2, -5.0f, m3)));
        float s = (r == 0) ? (1.0f / 704.0f) : (r == 1 ? (1.0f / 256.0f) : 1.0f);
        float* d = sM + n * 16 + r * 4;
        d[0] = p0 * s; d[1] = p1 * s; d[2] = p2 * s; d[3] = p3 * s;
    }
    __syncthreads();

    int gwarp = blockIdx.x * 8 + (tid >> 5);
    int lane  = tid & 31;
    int which = (lane >> 3) & 1;
    int cam   = lane & 7;
    bool proj_lane = (lane < 16) & (cam < NCAM);

    const char* b0 = (const char*)g_f0t + lane * 16;   // lane channel offset
    const char* b1 = (const char*)g_f1t + lane * 16;

    // Persistent loop: each warp handles task pairs gwarp, gwarp+NWARPS, ...
    for (int wpair = gwarp; wpair < NPAIR; wpair += NWARPS) {
        int t0 = wpair * 2;
        int task = t0 + which;

        // Projection: lanes 0-5 -> task A, lanes 8-13 -> task B.
        bool valid = false;
        float u = 0.f, v = 0.f;
        if (proj_lane) {
            int q = task >> 2;
            int p = task & 3;
            int hb = q >> 7;
            int wb = q & 127;
            const float* rp = refpts + ((size_t)((p * 128 + hb) * 128 + wb)) * 3;
            float rx = __ldg(rp + 0);
            float ry = __ldg(rp + 1);
            float rz = __ldg(rp + 2);

            const float* M = sM + cam * 16;
            float cz = fmaf(M[8], rx, fmaf(M[9], ry, fmaf(M[10], rz, M[11])));
            if (cz > EPSF) {
                float cx = fmaf(M[0], rx, fmaf(M[1], ry, fmaf(M[2], rz, M[3])));
                float cy = fmaf(M[4], rx, fmaf(M[5], ry, fmaf(M[6], rz, M[7])));
                float invz = __fdividef(1.0f, cz);
                u = cx * invz;
                v = cy * invz;
                valid = (u > 0.0f) & (u < 1.0f) & (v > 0.0f) & (v < 1.0f);
            }
        }

        unsigned vm = __ballot_sync(FULLMASK, valid);
        float* op = out + (size_t)t0 * CCH + lane * 4;

        task_gather(vm & 0x3Fu,        0, u, v, b0, b1, op);
        task_gather((vm >> 8) & 0x3Fu, 8, u, v, b0, b1, op + CCH);
    }
}

extern "C" void kernel_launch(void* const* d_in, const int* in_sizes, int n_in,
                              void* d_out, int out_size) {
    const float* refpts    = (const float*)d_in[0];   // [1,4,128,128,3]
    const float* feats0    = (const float*)d_in[1];   // [1,6,128,32,88]
    const float* feats1    = (const float*)d_in[2];   // [1,6,128,16,44]
    const float* lidar2img = (const float*)d_in[3];   // [1,6,4,4]
    float* out = (float*)d_out;                       // [1,16384,4,128]

    transpose_feats_kernel<<<NBLK0 + NBLK1, 256>>>(feats0, feats1);
    // Persistent single wave: 152 SMs x 8 blocks.
    bev_sample_kernel<<<NBLKMAIN, 256>>>(refpts, lidar2img, out);
}

// round 14
// speedup vs baseline: 1.2287x; 1.2287x over previous
#include <cuda_runtime.h>
#include <cuda_fp16.h>

#define NCAM 6
#define CCH  128
#define H0   32
#define W0   88
#define H1   16
#define W1   44
#define H0P  (H0+2)       // 34
#define W0P  (W0+2)       // 90
#define H1P  (H1+2)       // 18
#define W1P  (W1+2)       // 46
#define HW0  (H0*W0)      // 2816
#define HW1  (H1*W1)      // 704
#define QDIM 16384
#define PPTS 4
#define NTASK (QDIM * PPTS)
#define EPSF 1e-5f
#define FULLMASK 0xffffffffu

// Transposed + zero-padded FP16 feature cache: [N, H+2, W+2, C].
// Borders never written; __device__ globals zero-init => out-of-range
// bilinear corners read exact zeros (padding_mode='zeros').
__device__ __half g_f0t[NCAM * H0P * W0P * CCH];   // ~4.7 MB
__device__ __half g_f1t[NCAM * H1P * W1P * CCH];   // ~1.25 MB

__device__ __forceinline__ unsigned h2_as_u32(__half2 h) {
    unsigned r;
    memcpy(&r, &h, 4);
    return r;
}

// -------------------------------------------------------------------------
// SMEM-tiled transpose + fp32->fp16 convert:
// [C=128, HW] fp32 -> padded [H+2, W+2, C] fp16.
// -------------------------------------------------------------------------
#define NBLK0 (NCAM * 4 * (HW0/32))   // 2112
#define NBLK1 (NCAM * 4 * (HW1/32))   // 528

__global__ void __launch_bounds__(256)
transpose_feats_kernel(const float* __restrict__ f0,
                       const float* __restrict__ f1) {
    __shared__ float tile[32][33];

    int b = blockIdx.x;
    const float* __restrict__ src;
    __half* __restrict__ dst;
    int n, ct, hwt, HW, W, WP;
    if (b < NBLK0) {
        n = b / (4 * (HW0/32));
        int r = b % (4 * (HW0/32));
        ct = r & 3; hwt = r >> 2;
        src = f0; dst = g_f0t; HW = HW0; W = W0; WP = W0P;
    } else {
        b -= NBLK0;
        n = b / (4 * (HW1/32));
        int r = b % (4 * (HW1/32));
        ct = r & 3; hwt = r >> 2;
        src = f1; dst = g_f1t; HW = HW1; W = W1; WP = W1P;
    }

    {
        int c   = threadIdx.x >> 3;
        int hw4 = (threadIdx.x & 7) * 4;
        const float4 v = *reinterpret_cast<const float4*>(
            src + (size_t)n * CCH * HW + (size_t)(ct*32 + c) * HW + hwt*32 + hw4);
        tile[hw4 + 0][c] = v.x;
        tile[hw4 + 1][c] = v.y;
        tile[hw4 + 2][c] = v.z;
        tile[hw4 + 3][c] = v.w;
    }
    __syncthreads();

    {
        int hw = threadIdx.x >> 3;
        int c4 = (threadIdx.x & 7) * 4;
        __half2 h01 = __floats2half2_rn(tile[hw][c4 + 0], tile[hw][c4 + 1]);
        __half2 h23 = __floats2half2_rn(tile[hw][c4 + 2], tile[hw][c4 + 3]);
        int hwglob = hwt * 32 + hw;
        int h = hwglob / W;
        int w = hwglob - h * W;
        size_t HPWP = (size_t)(W == W0 ? H0P * W0P : H1P * W1P);
        size_t off = ((size_t)n * HPWP + (size_t)(h + 1) * WP + (w + 1)) * CCH
                   + ct * 32 + c4;
        uint2 st;
        st.x = h2_as_u32(h01);
        st.y = h2_as_u32(h23);
        *reinterpret_cast<uint2*>(dst + off) = st;
    }
}

// -------------------------------------------------------------------------
// Main sampling kernel: R7 structure (2 tasks/warp, lanes 0-5 / 8-13
// project), fp16 gathers (8B per lane per corner), fp32x2 accumulation.
// -------------------------------------------------------------------------

__device__ __forceinline__ void gacc(const char* __restrict__ base, int byteoff,
                                     float w,
                                     unsigned long long& aA, unsigned long long& aB) {
    uint2 h = *reinterpret_cast<const uint2*>(base + byteoff);   // 4 halfs
    __half2 h01, h23;
    memcpy(&h01, &h.x, 4);
    memcpy(&h23, &h.y, 4);
    float2 f01 = __half22float2(h01);
    float2 f23 = __half22float2(h23);
    unsigned long long vx, vy, wp;
    asm("mov.b64 %0, {%1, %2};" : "=l"(vx) : "f"(f01.x), "f"(f01.y));
    asm("mov.b64 %0, {%1, %2};" : "=l"(vy) : "f"(f23.x), "f"(f23.y));
    asm("mov.b64 %0, {%1, %1};" : "=l"(wp) : "f"(w));
    asm("fma.rn.f32x2 %0, %1, %2, %0;" : "+l"(aA) : "l"(vx), "l"(wp));
    asm("fma.rn.f32x2 %0, %1, %2, %0;" : "+l"(aB) : "l"(vy), "l"(wp));
}

// Clamp-free bilinear sample of one padded fp16 level; u,v warp-uniform.
__device__ __forceinline__ void sample_level(const char* __restrict__ base,
                                             float u, float v, int cambase,
                                             int Wl, int Hl, int WP,
                                             unsigned long long& aA,
                                             unsigned long long& aB) {
    float px = fmaf(u, (float)Wl, 0.5f);
    float py = fmaf(v, (float)Hl, 0.5f);
    int x0 = __float2int_rd(px);
    int y0 = __float2int_rd(py);
    float wx1 = px - __int2float_rn(x0);
    float wy1 = py - __int2float_rn(y0);
    float wx0 = 1.0f - wx1;
    float wy0 = 1.0f - wy1;

    int o00 = (cambase + y0 * WP + x0) << 8;   // *CCH*2 bytes
    int rowB = WP << 8;
    gacc(base, o00,              wx0 * wy0, aA, aB);
    gacc(base, o00 + 256,        wx1 * wy0, aA, aB);
    gacc(base, o00 + rowB,       wx0 * wy1, aA, aB);
    gacc(base, o00 + rowB + 256, wx1 * wy1, aA, aB);
}

__global__ void __launch_bounds__(256, 8)
bev_sample_kernel(const float* __restrict__ refpts,
                  const float* __restrict__ lidar2img,
                  float* __restrict__ out) {
    __shared__ float sM[NCAM * 16];
    if (threadIdx.x < NCAM * 16) sM[threadIdx.x] = lidar2img[threadIdx.x];
    __syncthreads();

    int wpair = blockIdx.x * 8 + (threadIdx.x >> 5);
    int lane  = threadIdx.x & 31;
    int t0 = wpair * 2;
    int which = (lane >> 3) & 1;
    int cam   = lane & 7;
    int task  = t0 + which;

    // Projection: lanes 0-5 -> task A, lanes 8-13 -> task B.
    bool valid = false;
    float u = 0.f, v = 0.f;
    if (lane < 16 && cam < NCAM) {
        int q = task >> 2;
        int p = task & 3;
        int hb = q >> 7;
        int wb = q & 127;
        const float* rp = refpts + ((size_t)((p * 128 + hb) * 128 + wb)) * 3;
        float X = __ldg(rp + 0) * 102.4f - 51.2f;
        float Y = __ldg(rp + 1) * 102.4f - 51.2f;
        float Z = __ldg(rp + 2) * 8.0f  - 5.0f;

        const float* M = sM + cam * 16;
        float cz = fmaf(M[8], X, fmaf(M[9], Y, fmaf(M[10], Z, M[11])));
        if (cz > EPSF) {
            float cx = fmaf(M[0], X, fmaf(M[1], Y, fmaf(M[2], Z, M[3])));
            float cy = fmaf(M[4], X, fmaf(M[5], Y, fmaf(M[6], Z, M[7])));
            float invz = __fdividef(1.0f, cz);
            u = cx * invz * (1.0f / 704.0f);
            v = cy * invz * (1.0f / 256.0f);
            valid = (u > 0.0f) & (u < 1.0f) & (v > 0.0f) & (v < 1.0f);
        }
    }

    unsigned vm  = __ballot_sync(FULLMASK, valid);
    unsigned vmA = vm & 0x3Fu;
    unsigned vmB = (vm >> 8) & 0x3Fu;

    const char* b0 = (const char*)g_f0t + lane * 8;   // lane channel offset
    const char* b1 = (const char*)g_f1t + lane * 8;

    // ---------------- Task A ----------------
    {
        unsigned long long aA = 0ull, aB = 0ull;
        int cnt = __popc(vmA);
#pragma unroll
        for (int c = 0; c < NCAM; c++) {
            if (vmA & (1u << c)) {
                float uu = __shfl_sync(FULLMASK, u, c);
                float vv = __shfl_sync(FULLMASK, v, c);
                sample_level(b0, uu, vv, c * (H0P * W0P), W0, H0, W0P, aA, aB);
                sample_level(b1, uu, vv, c * (H1P * W1P), W1, H1, W1P, aA, aB);
            }
        }
        float scale = 0.5f / fmaxf((float)cnt, 1.0f);
        float ax, ay, az, aw;
        asm("mov.b64 {%0, %1}, %2;" : "=f"(ax), "=f"(ay) : "l"(aA));
        asm("mov.b64 {%0, %1}, %2;" : "=f"(az), "=f"(aw) : "l"(aB));
        float4 o;
        o.x = ax * scale; o.y = ay * scale;
        o.z = az * scale; o.w = aw * scale;
        *reinterpret_cast<float4*>(out + (size_t)t0 * CCH + lane * 4) = o;
    }

    // ---------------- Task B ----------------
    {
        unsigned long long aA = 0ull, aB = 0ull;
        int cnt = __popc(vmB);
#pragma unroll
        for (int c = 0; c < NCAM; c++) {
            if (vmB & (1u << c)) {
                float uu = __shfl_sync(FULLMASK, u, c + 8);
                float vv = __shfl_sync(FULLMASK, v, c + 8);
                sample_level(b0, uu, vv, c * (H0P * W0P), W0, H0, W0P, aA, aB);
                sample_level(b1, uu, vv, c * (H1P * W1P), W1, H1, W1P, aA, aB);
            }
        }
        float scale = 0.5f / fmaxf((float)cnt, 1.0f);
        float ax, ay, az, aw;
        asm("mov.b64 {%0, %1}, %2;" : "=f"(ax), "=f"(ay) : "l"(aA));
        asm("mov.b64 {%0, %1}, %2;" : "=f"(az), "=f"(aw) : "l"(aB));
        float4 o;
        o.x = ax * scale; o.y = ay * scale;
        o.z = az * scale; o.w = aw * scale;
        *reinterpret_cast<float4*>(out + (size_t)(t0 + 1) * CCH + lane * 4) = o;
    }
}

extern "C" void kernel_launch(void* const* d_in, const int* in_sizes, int n_in,
                              void* d_out, int out_size) {
    const float* refpts    = (const float*)d_in[0];   // [1,4,128,128,3]
    const float* feats0    = (const float*)d_in[1];   // [1,6,128,32,88]
    const float* feats1    = (const float*)d_in[2];   // [1,6,128,16,44]
    const float* lidar2img = (const float*)d_in[3];   // [1,6,4,4]
    float* out = (float*)d_out;                       // [1,16384,4,128]

    transpose_feats_kernel<<<NBLK0 + NBLK1, 256>>>(feats0, feats1);
    // 2 tasks per warp, 8 warps per block -> 4096 blocks.
    bev_sample_kernel<<<NTASK / 16, 256>>>(refpts, lidar2img, out);
}

// round 15
// speedup vs baseline: 1.2432x; 1.0118x over previous
#include <cuda_runtime.h>
#include <cuda_fp16.h>

#define NCAM 6
#define CCH  128
#define H0   32
#define W0   88
#define H1   16
#define W1   44
#define H0P  (H0+2)       // 34
#define W0P  (W0+2)       // 90
#define H1P  (H1+2)       // 18
#define W1P  (W1+2)       // 46
#define HW0  (H0*W0)      // 2816
#define HW1  (H1*W1)      // 704
#define QDIM 16384
#define PPTS 4
#define NTASK (QDIM * PPTS)
#define EPSF 1e-5f
#define FULLMASK 0xffffffffu

// Transposed + zero-padded FP16 feature cache: [N, H+2, W+2, C].
// Borders never written; __device__ globals zero-init => out-of-range
// bilinear corners read exact zeros (padding_mode='zeros').
__device__ __half g_f0t[NCAM * H0P * W0P * CCH];   // ~4.7 MB
__device__ __half g_f1t[NCAM * H1P * W1P * CCH];   // ~1.25 MB

// -------------------------------------------------------------------------
// Fat-tile transpose + fp32->fp16: one block = full C=128 x 32-hw strip.
// Level0: 6 cams * 88 strips = 528 blocks; Level1: 6 * 22 = 132. Total 660.
// Per thread: 4x LDG.128 (fp32) -> smem -> 16 cvt+pack -> 2x STG.128 (fp16).
// -------------------------------------------------------------------------
#define NSTRIP0 (HW0 / 32)    // 88
#define NSTRIP1 (HW1 / 32)    // 22
#define NBLKT0  (NCAM * NSTRIP0)   // 528
#define NBLKT1  (NCAM * NSTRIP1)   // 132

__global__ void __launch_bounds__(256)
transpose_feats_kernel(const float* __restrict__ f0,
                       const float* __restrict__ f1) {
    __shared__ float tile[128][33];   // 16.9 KB, conflict-free column reads

    int b = blockIdx.x;
    const float* __restrict__ src;
    __half* __restrict__ dst;
    int n, strip, HW, W, WP;
    size_t HPWP;
    if (b < NBLKT0) {
        n = b / NSTRIP0; strip = b % NSTRIP0;
        src = f0; dst = g_f0t; HW = HW0; W = W0; WP = W0P;
        HPWP = (size_t)H0P * W0P;
    } else {
        b -= NBLKT0;
        n = b / NSTRIP1; strip = b % NSTRIP1;
        src = f1; dst = g_f1t; HW = HW1; W = W1; WP = W1P;
        HPWP = (size_t)H1P * W1P;
    }

    int t = threadIdx.x;
    // Read: 128 c-rows x 32 hw. Thread: c = (t>>3)+32i, col4 = (t&7)*4.
    {
        int col4 = (t & 7) * 4;
        const float* sp = src + (size_t)n * CCH * HW + strip * 32 + col4;
#pragma unroll
        for (int i = 0; i < 4; i++) {
            int c = (t >> 3) + 32 * i;
            float4 v = *reinterpret_cast<const float4*>(sp + (size_t)c * HW);
            tile[c][col4 + 0] = v.x;
            tile[c][col4 + 1] = v.y;
            tile[c][col4 + 2] = v.z;
            tile[c][col4 + 3] = v.w;
        }
    }
    __syncthreads();

    // Write: 32 hw-rows x 128 ch fp16 (256 B each).
    // Thread: hw = t>>3, cbase = (t&7)*16 -> two 16B stores.
    {
        int hw    = t >> 3;
        int cbase = (t & 7) * 16;
        int hwglob = strip * 32 + hw;
        int h = hwglob / W;
        int w = hwglob - h * W;
        __half* dp = dst + ((size_t)n * HPWP + (size_t)(h + 1) * WP + (w + 1)) * CCH
                   + cbase;
        uint4 s0, s1;
        unsigned* su = reinterpret_cast<unsigned*>(&s0);
#pragma unroll
        for (int k = 0; k < 4; k++) {
            __half2 hv = __floats2half2_rn(tile[cbase + 2*k][hw],
                                           tile[cbase + 2*k + 1][hw]);
            memcpy(su + k, &hv, 4);
        }
        unsigned* su1 = reinterpret_cast<unsigned*>(&s1);
#pragma unroll
        for (int k = 0; k < 4; k++) {
            __half2 hv = __floats2half2_rn(tile[cbase + 8 + 2*k][hw],
                                           tile[cbase + 9 + 2*k][hw]);
            memcpy(su1 + k, &hv, 4);
        }
        *reinterpret_cast<uint4*>(dp)     = s0;
        *reinterpret_cast<uint4*>(dp + 8) = s1;
    }
}

// -------------------------------------------------------------------------
// Main sampling kernel: R14 structure (2 tasks/warp, lanes 0-5 / 8-13
// project), fp16 gathers, plain-float FFMA accumulation.
// -------------------------------------------------------------------------

struct AccF { float x, y, z, w; };

__device__ __forceinline__ void gacc(const char* __restrict__ base, int byteoff,
                                     float w, AccF& a) {
    uint2 h = *reinterpret_cast<const uint2*>(base + byteoff);   // 4 halfs
    __half2 h01, h23;
    memcpy(&h01, &h.x, 4);
    memcpy(&h23, &h.y, 4);
    float2 f01 = __half22float2(h01);
    float2 f23 = __half22float2(h23);
    a.x = fmaf(w, f01.x, a.x);
    a.y = fmaf(w, f01.y, a.y);
    a.z = fmaf(w, f23.x, a.z);
    a.w = fmaf(w, f23.y, a.w);
}

// Clamp-free bilinear sample of one padded fp16 level; u,v warp-uniform.
__device__ __forceinline__ void sample_level(const char* __restrict__ base,
                                             float u, float v, int cambase,
                                             int Wl, int Hl, int WP,
                                             AccF& a) {
    float px = fmaf(u, (float)Wl, 0.5f);
    float py = fmaf(v, (float)Hl, 0.5f);
    int x0 = __float2int_rd(px);
    int y0 = __float2int_rd(py);
    float wx1 = px - __int2float_rn(x0);
    float wy1 = py - __int2float_rn(y0);
    float wx0 = 1.0f - wx1;
    float wy0 = 1.0f - wy1;

    int o00 = (cambase + y0 * WP + x0) << 8;   // *CCH*2 bytes
    int rowB = WP << 8;
    gacc(base, o00,              wx0 * wy0, a);
    gacc(base, o00 + 256,        wx1 * wy0, a);
    gacc(base, o00 + rowB,       wx0 * wy1, a);
    gacc(base, o00 + rowB + 256, wx1 * wy1, a);
}

__global__ void __launch_bounds__(256, 8)
bev_sample_kernel(const float* __restrict__ refpts,
                  const float* __restrict__ lidar2img,
                  float* __restrict__ out) {
    __shared__ float sM[NCAM * 16];
    if (threadIdx.x < NCAM * 16) sM[threadIdx.x] = lidar2img[threadIdx.x];
    __syncthreads();

    int wpair = blockIdx.x * 8 + (threadIdx.x >> 5);
    int lane  = threadIdx.x & 31;
    int t0 = wpair * 2;
    int which = (lane >> 3) & 1;
    int cam   = lane & 7;
    int task  = t0 + which;

    // Projection: lanes 0-5 -> task A, lanes 8-13 -> task B.
    bool valid = false;
    float u = 0.f, v = 0.f;
    if (lane < 16 && cam < NCAM) {
        int q = task >> 2;
        int p = task & 3;
        int hb = q >> 7;
        int wb = q & 127;
        const float* rp = refpts + ((size_t)((p * 128 + hb) * 128 + wb)) * 3;
        float X = __ldg(rp + 0) * 102.4f - 51.2f;
        float Y = __ldg(rp + 1) * 102.4f - 51.2f;
        float Z = __ldg(rp + 2) * 8.0f  - 5.0f;

        const float* M = sM + cam * 16;
        float cz = fmaf(M[8], X, fmaf(M[9], Y, fmaf(M[10], Z, M[11])));
        if (cz > EPSF) {
            float cx = fmaf(M[0], X, fmaf(M[1], Y, fmaf(M[2], Z, M[3])));
            float cy = fmaf(M[4], X, fmaf(M[5], Y, fmaf(M[6], Z, M[7])));
            float invz = __fdividef(1.0f, cz);
            u = cx * invz * (1.0f / 704.0f);
            v = cy * invz * (1.0f / 256.0f);
            valid = (u > 0.0f) & (u < 1.0f) & (v > 0.0f) & (v < 1.0f);
        }
    }

    unsigned vm  = __ballot_sync(FULLMASK, valid);
    unsigned vmA = vm & 0x3Fu;
    unsigned vmB = (vm >> 8) & 0x3Fu;

    const char* b0 = (const char*)g_f0t + lane * 8;   // lane channel offset
    const char* b1 = (const char*)g_f1t + lane * 8;

    // ---------------- Task A ----------------
    {
        AccF a = {0.f, 0.f, 0.f, 0.f};
        int cnt = __popc(vmA);
#pragma unroll
        for (int c = 0; c < NCAM; c++) {
            if (vmA & (1u << c)) {
                float uu = __shfl_sync(FULLMASK, u, c);
                float vv = __shfl_sync(FULLMASK, v, c);
                sample_level(b0, uu, vv, c * (H0P * W0P), W0, H0, W0P, a);
                sample_level(b1, uu, vv, c * (H1P * W1P), W1, H1, W1P, a);
            }
        }
        float scale = 0.5f / fmaxf((float)cnt, 1.0f);
        float4 o;
        o.x = a.x * scale; o.y = a.y * scale;
        o.z = a.z * scale; o.w = a.w * scale;
        *reinterpret_cast<float4*>(out + (size_t)t0 * CCH + lane * 4) = o;
    }

    // ---------------- Task B ----------------
    {
        AccF a = {0.f, 0.f, 0.f, 0.f};
        int cnt = __popc(vmB);
#pragma unroll
        for (int c = 0; c < NCAM; c++) {
            if (vmB & (1u << c)) {
                float uu = __shfl_sync(FULLMASK, u, c + 8);
                float vv = __shfl_sync(FULLMASK, v, c + 8);
                sample_level(b0, uu, vv, c * (H0P * W0P), W0, H0, W0P, a);
                sample_level(b1, uu, vv, c * (H1P * W1P), W1, H1, W1P, a);
            }
        }
        float scale = 0.5f / fmaxf((float)cnt, 1.0f);
        float4 o;
        o.x = a.x * scale; o.y = a.y * scale;
        o.z = a.z * scale; o.w = a.w * scale;
        *reinterpret_cast<float4*>(out + (size_t)(t0 + 1) * CCH + lane * 4) = o;
    }
}

extern "C" void kernel_launch(void* const* d_in, const int* in_sizes, int n_in,
                              void* d_out, int out_size) {
    const float* refpts    = (const float*)d_in[0];   // [1,4,128,128,3]
    const float* feats0    = (const float*)d_in[1];   // [1,6,128,32,88]
    const float* feats1    = (const float*)d_in[2];   // [1,6,128,16,44]
    const float* lidar2img = (const float*)d_in[3];   // [1,6,4,4]
    float* out = (float*)d_out;                       // [1,16384,4,128]

    transpose_feats_kernel<<<NBLKT0 + NBLKT1, 256>>>(feats0, feats1);
    // 2 tasks per warp, 8 warps per block -> 4096 blocks.
    bev_sample_kernel<<<NTASK / 16, 256>>>(refpts, lidar2img, out);
}